// round 1
// baseline (speedup 1.0000x reference)
#include <cuda_runtime.h>

#define NN 50000
#define NE 640000
#define DD 128

// ---------------- scratch (device globals; no allocations allowed) ----------
__device__ float g_A[NN * DD];     // node_h @ We1[0:128]     (src term)
__device__ float g_B[NN * DD];     // node_h @ We1[128:256]   (dst term)
__device__ float g_agg[NN * DD];   // segment_sum(relu_hidden)
__device__ float g_aggm[NN * DD];  // agg @ We2 + deg*be2
__device__ float g_hid[NN * DD];   // relu(aggm@Wn1a + node_h@Wn1b + bn1)
__device__ float g_deg[NN];        // in-degree (for be2 term)

typedef unsigned long long ull;

__device__ __forceinline__ ull pack2(float x) {
    ull r; unsigned u = __float_as_uint(x);
    asm("mov.b64 %0, {%1, %1};" : "=l"(r) : "r"(u));
    return r;
}
__device__ __forceinline__ void ffma2(ull &c, ull a, ull b) {
    asm("fma.rn.f32x2 %0, %1, %2, %0;" : "+l"(c) : "l"(a), "l"(b));
}
__device__ __forceinline__ float lo2(ull v) { return __uint_as_float((unsigned)v); }
__device__ __forceinline__ float hi2(ull v) { return __uint_as_float((unsigned)(v >> 32)); }

// ---------------- zero scratch -----------------------------------------------
__global__ void zero_kernel() {
    int i = blockIdx.x * blockDim.x + threadIdx.x;
    int stride = gridDim.x * blockDim.x;
    float4 z = make_float4(0.f, 0.f, 0.f, 0.f);
    for (int j = i; j < NN * DD / 4; j += stride) ((float4*)g_agg)[j] = z;
    for (int j = i; j < NN; j += stride) g_deg[j] = 0.f;
}

// ---------------- shared tile layout -----------------------------------------
// XsT: K-slice of X, TRANSPOSED [k][row], padded stride 132 so the transpose
// store has tolerable conflicts and LDS.128 row-pair reads stay 16B aligned.
// Ws:  32x128 slice of W, row-major (contiguous copy from global).
struct __align__(16) Smem {
    float XsT[32][132];
    float Ws[32][DD];
};

template<bool GUARD>
__device__ __forceinline__ void load_chunk(Smem& sm, const float* __restrict__ Xsrc,
                                           int row0, int kcc,
                                           const float* __restrict__ W, int kc,
                                           int M, int tid) {
    const float4* Wg = (const float4*)(W + (size_t)kc * DD);
    #pragma unroll
    for (int i = 0; i < 4; i++)
        ((float4*)sm.Ws)[i * 256 + tid] = Wg[i * 256 + tid];
    #pragma unroll
    for (int i = 0; i < 4; i++) {
        int t = i * 256 + tid;
        int r = t >> 3;            // 0..127 tile row
        int c4 = (t & 7) * 4;      // 0..28 k-offset
        float4 v = make_float4(0.f, 0.f, 0.f, 0.f);
        int gr = row0 + r;
        if (!GUARD || gr < M)
            v = *(const float4*)(Xsrc + (size_t)gr * DD + kcc + c4);
        sm.XsT[c4 + 0][r] = v.x;
        sm.XsT[c4 + 1][r] = v.y;
        sm.XsT[c4 + 2][r] = v.z;
        sm.XsT[c4 + 3][r] = v.w;
    }
}

// mainloop over one K-chunk of 32: acc[rp][c] packs (row 2rp, row 2rp+1) x col c
__device__ __forceinline__ void mma_chunk(const Smem& sm, ull acc[8][4], int cb, int rbase) {
    #pragma unroll
    for (int k = 0; k < 32; k++) {
        float4 bw = *(const float4*)&sm.Ws[k][cb];
        ull b0 = pack2(bw.x), b1 = pack2(bw.y), b2 = pack2(bw.z), b3 = pack2(bw.w);
        #pragma unroll
        for (int i = 0; i < 4; i++) {
            // 4 consecutive rows -> two row-pairs, one broadcast LDS.128
            ulonglong2 av = *(const ulonglong2*)&sm.XsT[k][rbase + 4 * i];
            ffma2(acc[2*i+0][0], av.x, b0); ffma2(acc[2*i+0][1], av.x, b1);
            ffma2(acc[2*i+0][2], av.x, b2); ffma2(acc[2*i+0][3], av.x, b3);
            ffma2(acc[2*i+1][0], av.y, b0); ffma2(acc[2*i+1][1], av.y, b1);
            ffma2(acc[2*i+1][2], av.y, b2); ffma2(acc[2*i+1][3], av.y, b3);
        }
    }
}

// ---------------- generic node-side GEMM -------------------------------------
// MODE 0: out = X@W
// MODE 1: out = X@W + bias
// MODE 2: out = relu(X@W + bias)          (X = concat(X1,X2) when Ktot=256)
// MODE 3: out = X@W + deg*be2
template<int MODE>
__global__ __launch_bounds__(256, 2)
void gemm_kernel(const float* __restrict__ X1, const float* __restrict__ X2,
                 const float* __restrict__ W, const float* __restrict__ bias,
                 const float* __restrict__ be2, float* __restrict__ out,
                 int M, int Ktot) {
    __shared__ Smem sm;
    int tid = threadIdx.x;
    int cx = tid & 31, ry = tid >> 5;
    int cb = cx * 4, rbase = ry * 16;
    int row0 = blockIdx.x * 128;

    ull acc[8][4];
    #pragma unroll
    for (int i = 0; i < 8; i++)
        #pragma unroll
        for (int j = 0; j < 4; j++) acc[i][j] = 0ull;

    for (int kc = 0; kc < Ktot; kc += 32) {
        const float* Xsrc = (kc & DD) ? X2 : X1;
        load_chunk<true>(sm, Xsrc, row0, kc & (DD - 1), W, kc, M, tid);
        __syncthreads();
        mma_chunk(sm, acc, cb, rbase);
        __syncthreads();
    }

    float bv0 = 0.f, bv1 = 0.f, bv2 = 0.f, bv3 = 0.f;
    if (MODE == 1 || MODE == 2) {
        float4 b = *(const float4*)(bias + cb);
        bv0 = b.x; bv1 = b.y; bv2 = b.z; bv3 = b.w;
    }
    float e0 = 0.f, e1 = 0.f, e2 = 0.f, e3 = 0.f;
    if (MODE == 3) {
        float4 b = *(const float4*)(be2 + cb);
        e0 = b.x; e1 = b.y; e2 = b.z; e3 = b.w;
    }

    #pragma unroll
    for (int rp = 0; rp < 8; rp++) {
        #pragma unroll
        for (int h = 0; h < 2; h++) {
            int gr = row0 + rbase + rp * 2 + h;
            if (gr >= M) continue;
            float o0 = h ? hi2(acc[rp][0]) : lo2(acc[rp][0]);
            float o1 = h ? hi2(acc[rp][1]) : lo2(acc[rp][1]);
            float o2 = h ? hi2(acc[rp][2]) : lo2(acc[rp][2]);
            float o3 = h ? hi2(acc[rp][3]) : lo2(acc[rp][3]);
            if (MODE == 1 || MODE == 2) { o0 += bv0; o1 += bv1; o2 += bv2; o3 += bv3; }
            if (MODE == 3) {
                float dg = g_deg[gr];
                o0 += dg * e0; o1 += dg * e1; o2 += dg * e2; o3 += dg * e3;
            }
            if (MODE == 2) {
                o0 = fmaxf(o0, 0.f); o1 = fmaxf(o1, 0.f);
                o2 = fmaxf(o2, 0.f); o3 = fmaxf(o3, 0.f);
            }
            *(float4*)(out + (size_t)gr * DD + cb) = make_float4(o0, o1, o2, o3);
        }
    }
}

// ---------------- edge kernel ------------------------------------------------
// hidden = relu(edge_h@We1c + A[src] + B[dst] + be1); red.add into g_agg[dst]
__global__ __launch_bounds__(256, 2)
void edge_kernel(const float* __restrict__ edge_h, const int* __restrict__ src,
                 const int* __restrict__ dst, const float* __restrict__ W,
                 const float* __restrict__ be1) {
    __shared__ Smem sm;
    __shared__ int se[128], de[128];
    int tid = threadIdx.x;
    int cx = tid & 31, ry = tid >> 5;
    int cb = cx * 4, rbase = ry * 16;
    int e0 = blockIdx.x * 128;

    if (tid < 128) { se[tid] = src[e0 + tid]; de[tid] = dst[e0 + tid]; }

    ull acc[8][4];
    #pragma unroll
    for (int i = 0; i < 8; i++)
        #pragma unroll
        for (int j = 0; j < 4; j++) acc[i][j] = 0ull;

    for (int kc = 0; kc < DD; kc += 32) {
        load_chunk<false>(sm, edge_h, e0, kc, W, kc, NE, tid);
        __syncthreads();
        mma_chunk(sm, acc, cb, rbase);
        __syncthreads();
    }

    float4 bev = *(const float4*)(be1 + cb);

    #pragma unroll
    for (int rp = 0; rp < 8; rp++) {
        #pragma unroll
        for (int h = 0; h < 2; h++) {
            int el = rbase + rp * 2 + h;
            int s = se[el], d = de[el];
            // warp lanes cover the whole 128-wide row -> fully coalesced L2 hits
            float4 av = *(const float4*)(g_A + (size_t)s * DD + cb);
            float4 bw = *(const float4*)(g_B + (size_t)d * DD + cb);
            float o0 = (h ? hi2(acc[rp][0]) : lo2(acc[rp][0])) + av.x + bw.x + bev.x;
            float o1 = (h ? hi2(acc[rp][1]) : lo2(acc[rp][1])) + av.y + bw.y + bev.y;
            float o2 = (h ? hi2(acc[rp][2]) : lo2(acc[rp][2])) + av.z + bw.z + bev.z;
            float o3 = (h ? hi2(acc[rp][3]) : lo2(acc[rp][3])) + av.w + bw.w + bev.w;
            o0 = fmaxf(o0, 0.f); o1 = fmaxf(o1, 0.f);
            o2 = fmaxf(o2, 0.f); o3 = fmaxf(o3, 0.f);
            float* agp = g_agg + (size_t)d * DD + cb;
            asm volatile("red.global.add.v4.f32 [%0], {%1,%2,%3,%4};"
                         :: "l"(agp), "f"(o0), "f"(o1), "f"(o2), "f"(o3) : "memory");
        }
    }
    if (cx == 0) {
        #pragma unroll
        for (int r = 0; r < 16; r++) atomicAdd(&g_deg[de[rbase + r]], 1.0f);
    }
}

// ---------------- launch -----------------------------------------------------
extern "C" void kernel_launch(void* const* d_in, const int* in_sizes, int n_in,
                              void* d_out, int out_size) {
    const float* node_h = (const float*)d_in[0];
    const float* edge_h = (const float*)d_in[1];
    const int*   src    = (const int*)d_in[2];
    const int*   dst    = (const int*)d_in[3];
    const float* We1    = (const float*)d_in[4];
    const float* be1    = (const float*)d_in[5];
    const float* We2    = (const float*)d_in[6];
    const float* be2    = (const float*)d_in[7];
    const float* Wn1    = (const float*)d_in[8];
    const float* bn1    = (const float*)d_in[9];
    const float* Wn2    = (const float*)d_in[10];
    const float* bn2    = (const float*)d_in[11];
    float* out = (float*)d_out;

    float *pA, *pB, *pAgg, *pAggm, *pHid;
    cudaGetSymbolAddress((void**)&pA,    g_A);
    cudaGetSymbolAddress((void**)&pB,    g_B);
    cudaGetSymbolAddress((void**)&pAgg,  g_agg);
    cudaGetSymbolAddress((void**)&pAggm, g_aggm);
    cudaGetSymbolAddress((void**)&pHid,  g_hid);

    int nblk = (NN + 127) / 128;   // 391

    zero_kernel<<<296, 256>>>();
    // A = node_h @ We1[0:128], B = node_h @ We1[128:256]
    gemm_kernel<0><<<nblk, 256>>>(node_h, nullptr, We1,            nullptr, nullptr, pA,    NN, DD);
    gemm_kernel<0><<<nblk, 256>>>(node_h, nullptr, We1 + DD * DD,  nullptr, nullptr, pB,    NN, DD);
    // per-edge hidden + segment sum (relu pushed before We2; We2 applied post-agg)
    edge_kernel<<<NE / 128, 256>>>(edge_h, src, dst, We1 + 2 * DD * DD, be1);
    // agg_m = agg @ We2 + deg*be2
    gemm_kernel<3><<<nblk, 256>>>(pAgg,   nullptr, We2, nullptr, be2,     pAggm, NN, DD);
    // hidden = relu([agg_m, node_h] @ Wn1 + bn1)
    gemm_kernel<2><<<nblk, 256>>>(pAggm,  node_h,  Wn1, bn1,     nullptr, pHid,  NN, 2 * DD);
    // out = hidden @ Wn2 + bn2
    gemm_kernel<1><<<nblk, 256>>>(pHid,   nullptr, Wn2, bn2,     nullptr, out,   NN, DD);
}

// round 11
// speedup vs baseline: 1.3510x; 1.3510x over previous
#include <cuda_runtime.h>
#include <cuda_bf16.h>
#include <cstdint>

#define NN 50000
#define NE 640000
#define DD 128
#define NTILE (NE / 128)   // 5000

// ---------------- device scratch --------------------------------------------
__device__ float g_A[NN * DD];     // node_h @ We1[0:128]
__device__ float g_B[NN * DD];     // node_h @ We1[128:256]
__device__ float g_agg[NN * DD];   // segment_sum(relu_hidden)
__device__ float g_aggm[NN * DD];  // agg @ We2 + deg*be2
__device__ float g_hid[NN * DD];
__device__ float g_deg[NN];
// 7 weight slices, hi/lo bf16, stored [n][k] (k contiguous)
__device__ __nv_bfloat16 g_Whi[7 * DD * DD];
__device__ __nv_bfloat16 g_Wlo[7 * DD * DD];

// ---------------- smem layout ------------------------------------------------
// A chunk: [128 rows][64 k] bf16, row stride SA=72 elements (144B: 8-row
// ldmatrix groups hit 8 distinct 16B banks -> conflict-free).
#define SA 72
#define AB 18432                 // 128*72*2 bytes per buffer
#define S_AH 0
#define S_AL AB
#define S_WH (2*AB)
#define S_WL (3*AB)
#define S_IDX (4*AB)             // se[128], de[128]
#define SMEM_BYTES (4*AB + 1024) // 74752

// ---------------- helpers ----------------------------------------------------
__device__ __forceinline__ uint32_t smem_u32(const void* p) {
    uint32_t a;
    asm("{ .reg .u64 t; cvta.to.shared.u64 t, %1; cvt.u32.u64 %0, t; }" : "=r"(a) : "l"(p));
    return a;
}
__device__ __forceinline__ void ldm4(uint32_t* r, uint32_t a) {
    asm volatile("ldmatrix.sync.aligned.m8n8.x4.shared.b16 {%0,%1,%2,%3}, [%4];"
        : "=r"(r[0]), "=r"(r[1]), "=r"(r[2]), "=r"(r[3]) : "r"(a));
}
__device__ __forceinline__ void mmabf(float* c, const uint32_t* a, uint32_t b0, uint32_t b1) {
    asm volatile("mma.sync.aligned.m16n8k16.row.col.f32.bf16.bf16.f32 "
        "{%0,%1,%2,%3}, {%4,%5,%6,%7}, {%8,%9}, {%0,%1,%2,%3};"
        : "+f"(c[0]), "+f"(c[1]), "+f"(c[2]), "+f"(c[3])
        : "r"(a[0]), "r"(a[1]), "r"(a[2]), "r"(a[3]), "r"(b0), "r"(b1));
}
__device__ __forceinline__ void red2(float* p, float x, float y) {
    asm volatile("red.global.add.v2.f32 [%0], {%1,%2};" :: "l"(p), "f"(x), "f"(y) : "memory");
}

// ---------------- small kernels ----------------------------------------------
__global__ void zero_kernel() {
    int i = blockIdx.x * blockDim.x + threadIdx.x;
    int stride = gridDim.x * blockDim.x;
    float4 z = make_float4(0.f, 0.f, 0.f, 0.f);
    for (int j = i; j < NN * DD / 4; j += stride) ((float4*)g_agg)[j] = z;
    for (int j = i; j < NN; j += stride) g_deg[j] = 0.f;
}

// split each weight slice into hi/lo bf16, transposed to [n][k]
__global__ void prep_kernel(const float* __restrict__ We1, const float* __restrict__ We2,
                            const float* __restrict__ Wn1, const float* __restrict__ Wn2) {
    int idx = blockIdx.x * blockDim.x + threadIdx.x;
    if (idx >= 7 * DD * DD) return;
    int s = idx >> 14, r = idx & 16383, k = r >> 7, n = r & 127;
    const float* base;
    switch (s) {
        case 0: base = We1;               break;
        case 1: base = We1 + DD * DD;     break;
        case 2: base = We1 + 2 * DD * DD; break;
        case 3: base = We2;               break;
        case 4: base = Wn1;               break;
        case 5: base = Wn1 + DD * DD;     break;
        default: base = Wn2;              break;
    }
    float w = base[k * DD + n];
    __nv_bfloat16 h = __float2bfloat16(w);
    __nv_bfloat16 l = __float2bfloat16(w - __bfloat162float(h));
    g_Whi[s * 16384 + n * DD + k] = h;
    g_Wlo[s * 16384 + n * DD + k] = l;
}

// ---------------- building blocks --------------------------------------------
// convert a [128 rows][64 k] fp32 chunk into hi/lo bf16 smem tiles
__device__ __forceinline__ void convert_chunk(char* sm, const float* __restrict__ X,
                                              int row0, int kc, int M, int tid, bool guard) {
    #pragma unroll
    for (int i = 0; i < 8; i++) {
        int f = i * 256 + tid;
        int row = f >> 4, k4 = (f & 15) * 4;
        float4 v = make_float4(0.f, 0.f, 0.f, 0.f);
        if (!guard || (row0 + row) < M)
            v = *(const float4*)(X + (size_t)(row0 + row) * DD + kc + k4);
        __nv_bfloat16 h0 = __float2bfloat16(v.x), h1 = __float2bfloat16(v.y);
        __nv_bfloat16 h2 = __float2bfloat16(v.z), h3 = __float2bfloat16(v.w);
        __nv_bfloat16 l0 = __float2bfloat16(v.x - __bfloat162float(h0));
        __nv_bfloat16 l1 = __float2bfloat16(v.y - __bfloat162float(h1));
        __nv_bfloat16 l2 = __float2bfloat16(v.z - __bfloat162float(h2));
        __nv_bfloat16 l3 = __float2bfloat16(v.w - __bfloat162float(h3));
        uint2 hp, lp;
        hp.x = ((uint32_t)__bfloat16_as_ushort(h1) << 16) | __bfloat16_as_ushort(h0);
        hp.y = ((uint32_t)__bfloat16_as_ushort(h3) << 16) | __bfloat16_as_ushort(h2);
        lp.x = ((uint32_t)__bfloat16_as_ushort(l1) << 16) | __bfloat16_as_ushort(l0);
        lp.y = ((uint32_t)__bfloat16_as_ushort(l3) << 16) | __bfloat16_as_ushort(l2);
        int off = (row * SA + k4) * 2;
        *(uint2*)(sm + S_AH + off) = hp;
        *(uint2*)(sm + S_AL + off) = lp;
    }
}

__device__ __forceinline__ void copyW_chunk(char* sm, const __nv_bfloat16* __restrict__ ghi,
                                            const __nv_bfloat16* __restrict__ glo,
                                            int kc, int tid) {
    #pragma unroll
    for (int i = 0; i < 8; i++) {
        int idx = i * 256 + tid;
        int n = idx >> 4, j = (idx & 15) * 4;
        int off = (n * SA + j) * 2;
        *(uint2*)(sm + S_WH + off) = *(const uint2*)(ghi + n * DD + kc + j);
        *(uint2*)(sm + S_WL + off) = *(const uint2*)(glo + n * DD + kc + j);
    }
}

// K=64 chunk of the bf16x3 warp MMA: terms AhBh, AlBh, AhBl
__device__ __forceinline__ void mma_chunk64(uint32_t sb, float C[4][4][4], int lane, int wm, int wn) {
    uint32_t aH = sb + S_AH + (((wm * 64 + (lane & 15)) * SA) + (lane >> 4) * 8) * 2;
    uint32_t bRow = wn * 32 + (lane & 7) + ((lane >> 4) << 3);
    uint32_t bH = sb + S_WH + ((bRow * SA) + ((lane >> 3) & 1) * 8) * 2;
    #pragma unroll
    for (int kk = 0; kk < 64; kk += 16) {
        uint32_t ah[4][4], bh[2][4];
        #pragma unroll
        for (int mf = 0; mf < 4; mf++) ldm4(ah[mf], aH + mf * (16 * SA * 2) + kk * 2);
        #pragma unroll
        for (int n2 = 0; n2 < 2; n2++) ldm4(bh[n2], bH + n2 * (16 * SA * 2) + kk * 2);
        #pragma unroll
        for (int mf = 0; mf < 4; mf++)
            #pragma unroll
            for (int nf = 0; nf < 4; nf++)
                mmabf(C[mf][nf], ah[mf], bh[nf >> 1][(nf & 1) * 2], bh[nf >> 1][(nf & 1) * 2 + 1]);
        {   // Al x Bh (reuse bh, fresh al regs)
            uint32_t al[4][4];
            #pragma unroll
            for (int mf = 0; mf < 4; mf++) ldm4(al[mf], aH + AB + mf * (16 * SA * 2) + kk * 2);
            #pragma unroll
            for (int mf = 0; mf < 4; mf++)
                #pragma unroll
                for (int nf = 0; nf < 4; nf++)
                    mmabf(C[mf][nf], al[mf], bh[nf >> 1][(nf & 1) * 2], bh[nf >> 1][(nf & 1) * 2 + 1]);
        }
        {   // Ah x Bl (overwrite bh with bl)
            #pragma unroll
            for (int n2 = 0; n2 < 2; n2++) ldm4(bh[n2], bH + AB + n2 * (16 * SA * 2) + kk * 2);
            #pragma unroll
            for (int mf = 0; mf < 4; mf++)
                #pragma unroll
                for (int nf = 0; nf < 4; nf++)
                    mmabf(C[mf][nf], ah[mf], bh[nf >> 1][(nf & 1) * 2], bh[nf >> 1][(nf & 1) * 2 + 1]);
        }
    }
}

// ---------------- node-side GEMM ---------------------------------------------
// MODE 0: out=X@W   1: +bias   2: relu(+bias)   3: +deg*bias
// NC: number of K=64 chunks (2 for K=128, 4 for K=256 concat [X1,X2])
template<int MODE, int NC>
__global__ __launch_bounds__(256, 2)
void tgemm(const float* __restrict__ X1, const float* __restrict__ X2,
           const __nv_bfloat16* __restrict__ whi, const __nv_bfloat16* __restrict__ wlo,
           const float* __restrict__ bias, float* __restrict__ out, int M) {
    extern __shared__ char sm[];
    uint32_t sb = smem_u32(sm);
    int tid = threadIdx.x, lane = tid & 31, wid = tid >> 5;
    int wm = wid & 1, wn = wid >> 1;
    int row0 = blockIdx.x * 128;

    float C[4][4][4];
    #pragma unroll
    for (int a = 0; a < 4; a++)
        #pragma unroll
        for (int b = 0; b < 4; b++)
            #pragma unroll
            for (int c = 0; c < 4; c++) C[a][b][c] = 0.f;

    #pragma unroll
    for (int c = 0; c < NC; c++) {
        if (c) __syncthreads();
        const float* X = (NC == 4 && c >= 2) ? X2 : X1;
        int kc = (c & 1) * 64;
        convert_chunk(sm, X, row0, kc, M, tid, true);
        copyW_chunk(sm, whi + (c >> 1) * 16384, wlo + (c >> 1) * 16384, kc, tid);
        __syncthreads();
        mma_chunk64(sb, C, lane, wm, wn);
    }

    int rl = lane >> 2, colb = wn * 32 + (lane & 3) * 2;
    float2 bz[4];
    if (MODE != 0) {
        #pragma unroll
        for (int nf = 0; nf < 4; nf++) bz[nf] = *(const float2*)(bias + colb + nf * 8);
    }
    #pragma unroll
    for (int mf = 0; mf < 4; mf++) {
        int ra = row0 + wm * 64 + mf * 16 + rl;
        #pragma unroll
        for (int h = 0; h < 2; h++) {
            int gr = ra + h * 8;
            if (gr >= M) continue;
            float dg = (MODE == 3) ? g_deg[gr] : 0.f;
            #pragma unroll
            for (int nf = 0; nf < 4; nf++) {
                int cc = colb + nf * 8;
                float o0 = C[mf][nf][h * 2 + 0];
                float o1 = C[mf][nf][h * 2 + 1];
                if (MODE == 1 || MODE == 2) { o0 += bz[nf].x; o1 += bz[nf].y; }
                if (MODE == 3) { o0 += dg * bz[nf].x; o1 += dg * bz[nf].y; }
                if (MODE == 2) { o0 = fmaxf(o0, 0.f); o1 = fmaxf(o1, 0.f); }
                *(float2*)(out + (size_t)gr * DD + cc) = make_float2(o0, o1);
            }
        }
    }
}

// ---------------- edge kernel ------------------------------------------------
// hidden = relu(edge_h@We1c + A[src] + B[dst] + be1); red.add into g_agg[dst]
__global__ __launch_bounds__(256, 2)
void edge_hmma(const float* __restrict__ edge_h, const int* __restrict__ src,
               const int* __restrict__ dst, const __nv_bfloat16* __restrict__ whi,
               const __nv_bfloat16* __restrict__ wlo, const float* __restrict__ be1) {
    extern __shared__ char sm[];
    uint32_t sb = smem_u32(sm);
    int tid = threadIdx.x, lane = tid & 31, wid = tid >> 5;
    int wm = wid & 1, wn = wid >> 1;
    int e0 = blockIdx.x * 128;
    int* se = (int*)(sm + S_IDX);
    int* de = se + 128;
    if (tid < 128) { se[tid] = src[e0 + tid]; de[tid] = dst[e0 + tid]; }

    float C[4][4][4];
    #pragma unroll
    for (int a = 0; a < 4; a++)
        #pragma unroll
        for (int b = 0; b < 4; b++)
            #pragma unroll
            for (int c = 0; c < 4; c++) C[a][b][c] = 0.f;

    #pragma unroll
    for (int c = 0; c < 2; c++) {
        if (c) __syncthreads();
        convert_chunk(sm, edge_h, e0, c * 64, NE, tid, false);
        copyW_chunk(sm, whi, wlo, c * 64, tid);
        __syncthreads();
        mma_chunk64(sb, C, lane, wm, wn);
    }

    int rl = lane >> 2, colb = wn * 32 + (lane & 3) * 2;
    float2 be[4];
    #pragma unroll
    for (int nf = 0; nf < 4; nf++) be[nf] = *(const float2*)(be1 + colb + nf * 8);

    #pragma unroll
    for (int mf = 0; mf < 4; mf++) {
        int rbase = wm * 64 + mf * 16 + rl;
        #pragma unroll
        for (int h = 0; h < 2; h++) {
            int row = rbase + h * 8;
            int s = se[row], d = de[row];
            const float* ag = g_A + (size_t)s * DD;
            const float* bg = g_B + (size_t)d * DD;
            float* agp = g_agg + (size_t)d * DD;
            #pragma unroll
            for (int nf = 0; nf < 4; nf++) {
                int cc = colb + nf * 8;
                float2 av = *(const float2*)(ag + cc);
                float2 bv = *(const float2*)(bg + cc);
                float o0 = C[mf][nf][h * 2 + 0] + av.x + bv.x + be[nf].x;
                float o1 = C[mf][nf][h * 2 + 1] + av.y + bv.y + be[nf].y;
                o0 = fmaxf(o0, 0.f); o1 = fmaxf(o1, 0.f);
                red2(agp + cc, o0, o1);
            }
        }
    }
    // in-degree (each row counted exactly once: wn==0 warps, one lane per row)
    if (wn == 0 && (lane & 3) == 0) {
        #pragma unroll
        for (int mf = 0; mf < 4; mf++) {
            atomicAdd(&g_deg[de[wm * 64 + mf * 16 + rl]], 1.0f);
            atomicAdd(&g_deg[de[wm * 64 + mf * 16 + rl + 8]], 1.0f);
        }
    }
}

// ---------------- launch -----------------------------------------------------
extern "C" void kernel_launch(void* const* d_in, const int* in_sizes, int n_in,
                              void* d_out, int out_size) {
    const float* node_h = (const float*)d_in[0];
    const float* edge_h = (const float*)d_in[1];
    const int*   src    = (const int*)d_in[2];
    const int*   dst    = (const int*)d_in[3];
    const float* We1    = (const float*)d_in[4];
    const float* be1    = (const float*)d_in[5];
    const float* We2    = (const float*)d_in[6];
    const float* be2    = (const float*)d_in[7];
    const float* Wn1    = (const float*)d_in[8];
    const float* bn1    = (const float*)d_in[9];
    const float* Wn2    = (const float*)d_in[10];
    const float* bn2    = (const float*)d_in[11];
    float* out = (float*)d_out;

    float *pA, *pB, *pAgg, *pAggm, *pHid;
    __nv_bfloat16 *pWhi, *pWlo;
    cudaGetSymbolAddress((void**)&pA,    g_A);
    cudaGetSymbolAddress((void**)&pB,    g_B);
    cudaGetSymbolAddress((void**)&pAgg,  g_agg);
    cudaGetSymbolAddress((void**)&pAggm, g_aggm);
    cudaGetSymbolAddress((void**)&pHid,  g_hid);
    cudaGetSymbolAddress((void**)&pWhi,  g_Whi);
    cudaGetSymbolAddress((void**)&pWlo,  g_Wlo);

    cudaFuncSetAttribute(tgemm<0,2>, cudaFuncAttributeMaxDynamicSharedMemorySize, SMEM_BYTES);
    cudaFuncSetAttribute(tgemm<1,2>, cudaFuncAttributeMaxDynamicSharedMemorySize, SMEM_BYTES);
    cudaFuncSetAttribute(tgemm<2,4>, cudaFuncAttributeMaxDynamicSharedMemorySize, SMEM_BYTES);
    cudaFuncSetAttribute(tgemm<3,2>, cudaFuncAttributeMaxDynamicSharedMemorySize, SMEM_BYTES);
    cudaFuncSetAttribute(edge_hmma,  cudaFuncAttributeMaxDynamicSharedMemorySize, SMEM_BYTES);

    int nblk = (NN + 127) / 128;   // 391

    prep_kernel<<<(7 * DD * DD + 255) / 256, 256>>>(We1, We2, Wn1, Wn2);
    zero_kernel<<<296, 256>>>();
    // g_A = node_h @ We1a ; g_B = node_h @ We1b
    tgemm<0,2><<<nblk, 256, SMEM_BYTES>>>(node_h, nullptr, pWhi + 0 * 16384, pWlo + 0 * 16384, nullptr, pA, NN);
    tgemm<0,2><<<nblk, 256, SMEM_BYTES>>>(node_h, nullptr, pWhi + 1 * 16384, pWlo + 1 * 16384, nullptr, pB, NN);
    // edge: hidden = relu(edge_h@We1c + A[src] + B[dst] + be1) -> red into g_agg[dst]
    edge_hmma<<<NTILE, 256, SMEM_BYTES>>>(edge_h, src, dst, pWhi + 2 * 16384, pWlo + 2 * 16384, be1);
    // aggm = agg @ We2 + deg*be2
    tgemm<3,2><<<nblk, 256, SMEM_BYTES>>>(pAgg, nullptr, pWhi + 3 * 16384, pWlo + 3 * 16384, be2, pAggm, NN);
    // hid = relu([aggm, node_h] @ Wn1 + bn1)
    tgemm<2,4><<<nblk, 256, SMEM_BYTES>>>(pAggm, node_h, pWhi + 4 * 16384, pWlo + 4 * 16384, bn1, pHid, NN);
    // out = hid @ Wn2 + bn2
    tgemm<1,2><<<nblk, 256, SMEM_BYTES>>>(pHid, nullptr, pWhi + 6 * 16384, pWlo + 6 * 16384, bn2, out, NN);
}